// round 3
// baseline (speedup 1.0000x reference)
#include <cuda_runtime.h>
#include <cstdint>

#define N_NODES 8192
#define N_EDGES 32768
#define MUL_SC  32
#define MUL_VC  16
#define DIMF    80
#define NUM_RBF 16
#define HIDF    64
#define WNUMF   2560
#define TE      16

// scratch (device globals: allocation-free)
__device__ float g_agg[N_NODES * DIMF];
__device__ float g_cnt[N_NODES];

__device__ __forceinline__ unsigned long long pack2(float x) {
    unsigned long long r;
    asm("mov.b64 %0, {%1, %1};" : "=l"(r) : "r"(__float_as_uint(x)));
    return r;
}
__device__ __forceinline__ unsigned long long ffma2(unsigned long long a,
                                                    unsigned long long b,
                                                    unsigned long long c) {
    unsigned long long d;
    asm("fma.rn.f32x2 %0, %1, %2, %3;" : "=l"(d) : "l"(a), "l"(b), "l"(c));
    return d;
}

// ew[e] (packed pairs, 8x u64 = 16 edges) = b2[j] + sum_h hid[e][h] * W2[h][j]
__device__ __forceinline__ void mlp2_col(const float* __restrict__ W2,
                                         const float* __restrict__ b2,
                                         int j, const float* sm_hid,
                                         unsigned long long* ew) {
    unsigned long long bi = pack2(__ldg(b2 + j));
#pragma unroll
    for (int p = 0; p < 8; p++) ew[p] = bi;
    const float* wc = W2 + j;
#pragma unroll 16
    for (int hh = 0; hh < HIDF; hh++) {
        unsigned long long wp = pack2(__ldg(wc));
        wc += WNUMF;
        const ulonglong2* hp =
            reinterpret_cast<const ulonglong2*>(sm_hid + hh * TE);
        ulonglong2 a0 = hp[0], a1 = hp[1], a2 = hp[2], a3 = hp[3];
        ew[0] = ffma2(a0.x, wp, ew[0]);
        ew[1] = ffma2(a0.y, wp, ew[1]);
        ew[2] = ffma2(a1.x, wp, ew[2]);
        ew[3] = ffma2(a1.y, wp, ew[3]);
        ew[4] = ffma2(a2.x, wp, ew[4]);
        ew[5] = ffma2(a2.y, wp, ew[5]);
        ew[6] = ffma2(a3.x, wp, ew[6]);
        ew[7] = ffma2(a3.y, wp, ew[7]);
    }
}

__global__ void zero_kernel() {
    int i = blockIdx.x * 256 + threadIdx.x;
    if (i < N_NODES * DIMF) g_agg[i] = 0.0f;
    if (i < N_NODES) g_cnt[i] = 0.0f;
}

__global__ __launch_bounds__(256) void edge_kernel(
    const float* __restrict__ h, const float* __restrict__ pos,
    const int* __restrict__ ei, const float* __restrict__ means,
    const float* __restrict__ betas, const float* __restrict__ W1,
    const float* __restrict__ b1, const float* __restrict__ W2,
    const float* __restrict__ b2) {
    __shared__ __align__(16) float sm_hid[HIDF * TE];       // [h][e]
    __shared__ __align__(16) float sm_facS[48 * TE];        // sA[0..31], dotP[32..47]
    __shared__ __align__(16) float sm_sB[32 * TE];
    __shared__ __align__(16) float sm_vP[16 * 3 * TE];      // [u][d][e]
    __shared__ __align__(16) float sm_crP[16 * 3 * TE];
    __shared__ float sm_y1[TE * 4];
    __shared__ float sm_rbf[TE * NUM_RBF];
    __shared__ float sm_expd[TE];
    __shared__ float sm_cut[TE];
    __shared__ int   sm_dst[TE];
    __shared__ int   sm_src[TE];
    __shared__ __align__(16) float sm_redS[4 * 32 * TE];     // [wp][w][e]
    __shared__ __align__(16) float sm_redQ[4 * 16 * TE];     // [q][w'][e]
    __shared__ __align__(16) float sm_redV[4 * 16 * 3 * TE]; // [q][w'][d][e]

    const int tid = threadIdx.x;
    const int lane = tid & 31;
    const int warp = tid >> 5;
    const int e0 = blockIdx.x * TE;

    // ---- Stage A1: geometry per edge (16 threads) ----
    if (tid < TE) {
        int eg = e0 + tid;
        int s = ei[eg], dd = ei[N_EDGES + eg];
        float vx = pos[dd * 3 + 0] - pos[s * 3 + 0];
        float vy = pos[dd * 3 + 1] - pos[s * 3 + 1];
        float vz = pos[dd * 3 + 2] - pos[s * 3 + 2];
        float d = sqrtf(vx * vx + vy * vy + vz * vz + 1e-12f);
        float inv = 1.7320508075688772f / d;  // sqrt(3)/d
        sm_y1[tid * 4 + 0] = vx * inv;
        sm_y1[tid * 4 + 1] = vy * inv;
        sm_y1[tid * 4 + 2] = vz * inv;
        sm_expd[tid] = expf(-d);  // ALPHA = 1
        sm_cut[tid] =
            (d < 5.0f) ? 0.5f * (cosf(d * 0.6283185307179586f) + 1.0f) : 0.0f;
        sm_src[tid] = s;
        sm_dst[tid] = dd;
    }
    __syncthreads();

    // ---- Stage A2: rbf (256 threads: e x r) ----
    {
        int e = tid >> 4, r = tid & 15;
        float t0 = sm_expd[e] - __ldg(means + r);
        sm_rbf[e * 16 + r] = expf(-__ldg(betas + r) * t0 * t0) * sm_cut[e];
    }
    __syncthreads();

    // ---- Stage B: hid = silu(rbf @ W1 + b1) ----
    {
        int e = tid >> 4, kk = tid & 15;
#pragma unroll
        for (int i = 0; i < 4; i++) {
            int k = kk + 16 * i;
            float a = __ldg(b1 + k);
#pragma unroll
            for (int r = 0; r < 16; r++)
                a += sm_rbf[e * 16 + r] * __ldg(W1 + r * HIDF + k);
            float sg = 1.0f / (1.0f + expf(-a));
            sm_hid[k * TE + e] = a * sg;
        }
    }
    // ---- Stage C: prescaled left factors ----
    {
        int e = tid >> 4, t = tid & 15;
        const float* hr = h + (size_t)sm_src[e] * DIMF;
        const float cS = 0.125f;                 // 1/(sqrt32*sqrt2)
        const float cQ = 0.10206207261596575f;   // 1/(sqrt32*sqrt3)
        const float cD = 0.17677669529663687f;   // 1/(sqrt16*sqrt2)
        const float cV = 0.14433756729740643f;   // 1/(sqrt16*sqrt3)
        const float cX = 0.10206207261596575f;   // 1/(sqrt2*sqrt16*sqrt3)
        float s0 = hr[t], s1 = hr[t + 16];
        sm_facS[t * TE + e] = s0 * cS;
        sm_facS[(t + 16) * TE + e] = s1 * cS;
        sm_sB[t * TE + e] = s0 * cQ;
        sm_sB[(t + 16) * TE + e] = s1 * cQ;
        float v0 = hr[32 + 3 * t + 0];
        float v1 = hr[32 + 3 * t + 1];
        float v2 = hr[32 + 3 * t + 2];
        sm_vP[(t * 3 + 0) * TE + e] = v0 * cV;
        sm_vP[(t * 3 + 1) * TE + e] = v1 * cV;
        sm_vP[(t * 3 + 2) * TE + e] = v2 * cV;
        float y0 = sm_y1[e * 4 + 0], y1v = sm_y1[e * 4 + 1],
              y2 = sm_y1[e * 4 + 2];
        float dt = (v0 * y0 + v1 * y1v + v2 * y2) * 0.5773502691896258f; // /sqrt3
        sm_facS[(32 + t) * TE + e] = dt * cD;
        float c0 = v1 * y2 - v2 * y1v;
        float c1 = v2 * y0 - v0 * y2;
        float c2 = v0 * y1v - v1 * y0;
        sm_crP[(t * 3 + 0) * TE + e] = c0 * cX;
        sm_crP[(t * 3 + 1) * TE + e] = c1 * cX;
        sm_crP[(t * 3 + 2) * TE + e] = c2 * cX;
    }
    __syncthreads();

    // ---- Main fused GEMM + consume ----
    unsigned long long ew[8];
    if (warp < 4) {
        // ss (groups 0..31, u=i) + vv0 (groups 56..71, u=i-32); w = lane
        unsigned long long accS[8] = {};
#pragma unroll 1
        for (int t = 0; t < 12; t++) {
            int i = warp * 12 + t;
            int g = (i < 32) ? i : (i + 24);
            int j = g * 32 + lane;
            mlp2_col(W2, b2, j, sm_hid, ew);
            const ulonglong2* fp =
                reinterpret_cast<const ulonglong2*>(sm_facS + i * TE);
            ulonglong2 f0 = fp[0], f1 = fp[1], f2 = fp[2], f3 = fp[3];
            accS[0] = ffma2(ew[0], f0.x, accS[0]);
            accS[1] = ffma2(ew[1], f0.y, accS[1]);
            accS[2] = ffma2(ew[2], f1.x, accS[2]);
            accS[3] = ffma2(ew[3], f1.y, accS[3]);
            accS[4] = ffma2(ew[4], f2.x, accS[4]);
            accS[5] = ffma2(ew[5], f2.y, accS[5]);
            accS[6] = ffma2(ew[6], f3.x, accS[6]);
            accS[7] = ffma2(ew[7], f3.y, accS[7]);
        }
        unsigned long long* rs = reinterpret_cast<unsigned long long*>(
            sm_redS + (warp * 32 + lane) * TE);
#pragma unroll
        for (int p = 0; p < 8; p++) rs[p] = accS[p];
    } else if (warp < 6) {
        // sv block (groups 32..47): q2 accumulation; w' = lane&15
        int wr = warp - 4;
        unsigned long long accQ[8] = {};
#pragma unroll 1
        for (int t = 0; t < 8; t++) {
            int k = wr * 8 + t;
            int g = 32 + k;
            int u = 2 * k + (lane >> 4);
            int j = g * 32 + lane;
            mlp2_col(W2, b2, j, sm_hid, ew);
            const ulonglong2* fp =
                reinterpret_cast<const ulonglong2*>(sm_sB + u * TE);
            ulonglong2 f0 = fp[0], f1 = fp[1], f2 = fp[2], f3 = fp[3];
            accQ[0] = ffma2(ew[0], f0.x, accQ[0]);
            accQ[1] = ffma2(ew[1], f0.y, accQ[1]);
            accQ[2] = ffma2(ew[2], f1.x, accQ[2]);
            accQ[3] = ffma2(ew[3], f1.y, accQ[3]);
            accQ[4] = ffma2(ew[4], f2.x, accQ[4]);
            accQ[5] = ffma2(ew[5], f2.y, accQ[5]);
            accQ[6] = ffma2(ew[6], f3.x, accQ[6]);
            accQ[7] = ffma2(ew[7], f3.y, accQ[7]);
        }
        int q = wr * 2 + (lane >> 4);
        int w = lane & 15;
        unsigned long long* rq = reinterpret_cast<unsigned long long*>(
            sm_redQ + (q * 16 + w) * TE);
#pragma unroll
        for (int p = 0; p < 8; p++) rq[p] = accQ[p];
    } else {
        // warp 6: vs (groups 48..55, fac=vP); warp 7: vv1 (72..79, fac=crP)
        const int isV1 = (warp == 7);
        const float* fac = isV1 ? sm_crP : sm_vP;
        const int gbase = isV1 ? 72 : 48;
        unsigned long long accV[24] = {};  // [d][p]
#pragma unroll 1
        for (int t = 0; t < 8; t++) {
            int g = gbase + t;
            int u = 2 * t + (lane >> 4);
            int j = g * 32 + lane;
            mlp2_col(W2, b2, j, sm_hid, ew);
#pragma unroll
            for (int d = 0; d < 3; d++) {
                const ulonglong2* fp = reinterpret_cast<const ulonglong2*>(
                    fac + (u * 3 + d) * TE);
                ulonglong2 f0 = fp[0], f1 = fp[1], f2 = fp[2], f3 = fp[3];
                accV[d * 8 + 0] = ffma2(ew[0], f0.x, accV[d * 8 + 0]);
                accV[d * 8 + 1] = ffma2(ew[1], f0.y, accV[d * 8 + 1]);
                accV[d * 8 + 2] = ffma2(ew[2], f1.x, accV[d * 8 + 2]);
                accV[d * 8 + 3] = ffma2(ew[3], f1.y, accV[d * 8 + 3]);
                accV[d * 8 + 4] = ffma2(ew[4], f2.x, accV[d * 8 + 4]);
                accV[d * 8 + 5] = ffma2(ew[5], f2.y, accV[d * 8 + 5]);
                accV[d * 8 + 6] = ffma2(ew[6], f3.x, accV[d * 8 + 6]);
                accV[d * 8 + 7] = ffma2(ew[7], f3.y, accV[d * 8 + 7]);
            }
        }
        int q = (warp - 6) * 2 + (lane >> 4);
        int w = lane & 15;
#pragma unroll
        for (int d = 0; d < 3; d++) {
            unsigned long long* rv = reinterpret_cast<unsigned long long*>(
                sm_redV + ((q * 16 + w) * 3 + d) * TE);
#pragma unroll
            for (int p = 0; p < 8; p++) rv[p] = accV[d * 8 + p];
        }
    }
    __syncthreads();

    // ---- Assemble messages + global atomic aggregation ----
    {
        int e = tid >> 4, t16 = tid & 15;
        int dd = sm_dst[e];
        float* aggrow = g_agg + (size_t)dd * DIMF;
#pragma unroll
        for (int i = 0; i < 5; i++) {
            int k = t16 + 16 * i;
            float val;
            if (k < 32) {
                val = sm_redS[(0 * 32 + k) * TE + e] +
                      sm_redS[(1 * 32 + k) * TE + e] +
                      sm_redS[(2 * 32 + k) * TE + e] +
                      sm_redS[(3 * 32 + k) * TE + e];
            } else {
                int kk = k - 32;
                int w = kk / 3;
                int d = kk - 3 * w;
                float q2 = sm_redQ[(0 * 16 + w) * TE + e] +
                           sm_redQ[(1 * 16 + w) * TE + e] +
                           sm_redQ[(2 * 16 + w) * TE + e] +
                           sm_redQ[(3 * 16 + w) * TE + e];
                float vv = sm_redV[((0 * 16 + w) * 3 + d) * TE + e] +
                           sm_redV[((1 * 16 + w) * 3 + d) * TE + e] +
                           sm_redV[((2 * 16 + w) * 3 + d) * TE + e] +
                           sm_redV[((3 * 16 + w) * 3 + d) * TE + e];
                val = q2 * sm_y1[e * 4 + d] + vv;
            }
            atomicAdd(aggrow + k, val);
        }
        if (t16 == 0) atomicAdd(g_cnt + dd, 1.0f);
    }
}

__global__ void combine_kernel(const float* __restrict__ h,
                               const float* __restrict__ Wss,
                               const float* __restrict__ Wvv,
                               float* __restrict__ out) {
    int idx = blockIdx.x * 256 + threadIdx.x;
    if (idx >= N_NODES * DIMF) return;
    int n = idx / DIMF;
    int k = idx - n * DIMF;
    const float* hr = h + (size_t)n * DIMF;
    float si;
    if (k < 32) {
        float s = 0.0f;
#pragma unroll
        for (int u = 0; u < 32; u++) s += hr[u] * __ldg(Wss + u * 32 + k);
        si = s * 0.17677669529663687f;  // 1/sqrt(32)
    } else {
        int kk = k - 32;
        int w = kk / 3;
        int d = kk - 3 * w;
        float s = 0.0f;
#pragma unroll
        for (int u = 0; u < 16; u++)
            s += hr[32 + 3 * u + d] * __ldg(Wvv + u * 16 + w);
        si = s * 0.25f;  // 1/sqrt(16)
    }
    float c = g_cnt[n];
    float a = g_agg[idx] / fmaxf(c, 1.0f);
    out[idx] = a + si + hr[k];
}

extern "C" void kernel_launch(void* const* d_in, const int* in_sizes, int n_in,
                              void* d_out, int out_size) {
    const float* h     = (const float*)d_in[0];
    const float* pos   = (const float*)d_in[1];
    const int*   ei    = (const int*)d_in[2];
    const float* means = (const float*)d_in[3];
    const float* betas = (const float*)d_in[4];
    const float* W1    = (const float*)d_in[5];
    const float* b1    = (const float*)d_in[6];
    const float* W2    = (const float*)d_in[7];
    const float* b2    = (const float*)d_in[8];
    const float* Wss   = (const float*)d_in[9];
    const float* Wvv   = (const float*)d_in[10];
    float* out = (float*)d_out;

    zero_kernel<<<(N_NODES * DIMF + 255) / 256, 256>>>();
    edge_kernel<<<N_EDGES / TE, 256>>>(h, pos, ei, means, betas, W1, b1, W2, b2);
    combine_kernel<<<(N_NODES * DIMF + 255) / 256, 256>>>(h, Wss, Wvv, out);
}

// round 5
// speedup vs baseline: 1.8049x; 1.8049x over previous
#include <cuda_runtime.h>
#include <cstdint>

#define N_NODES 8192
#define N_EDGES 32768
#define DIMF    80
#define NUM_RBF 16
#define HIDF    64
#define WNUMF   2560
#define TE      16

// scratch (device globals: allocation-free)
__device__ float g_agg[N_NODES * DIMF];
__device__ float g_cnt[N_NODES];

// per-warp schedule: 10 (group, type) entries per warp. type: 0=S, 1=Q, 2=V
// groups: ss 0..31 | sv 32..47 | vs 48..55 | vv0 56..71 | vv1 72..79
// S-type = ss + vv0 (48), Q-type = sv (16), V-type = vs + vv1 (16)
__constant__ unsigned short c_sched[80] = {
    // w0: ss 0-9
    0, 1, 2, 3, 4, 5, 6, 7, 8, 9,
    // w1: ss 10-19
    10, 11, 12, 13, 14, 15, 16, 17, 18, 19,
    // w2: ss 20-29
    20, 21, 22, 23, 24, 25, 26, 27, 28, 29,
    // w3: ss 30,31 + vv0 56-63
    30, 31, 56, 57, 58, 59, 60, 61, 62, 63,
    // w4: vv0 64-71 + sv 32,33
    64, 65, 66, 67, 68, 69, 70, 71,
    (unsigned short)(32 | (1 << 8)), (unsigned short)(33 | (1 << 8)),
    // w5: sv 34-43
    (unsigned short)(34 | (1 << 8)), (unsigned short)(35 | (1 << 8)),
    (unsigned short)(36 | (1 << 8)), (unsigned short)(37 | (1 << 8)),
    (unsigned short)(38 | (1 << 8)), (unsigned short)(39 | (1 << 8)),
    (unsigned short)(40 | (1 << 8)), (unsigned short)(41 | (1 << 8)),
    (unsigned short)(42 | (1 << 8)), (unsigned short)(43 | (1 << 8)),
    // w6: sv 44-47 + vs 48-53
    (unsigned short)(44 | (1 << 8)), (unsigned short)(45 | (1 << 8)),
    (unsigned short)(46 | (1 << 8)), (unsigned short)(47 | (1 << 8)),
    (unsigned short)(48 | (2 << 8)), (unsigned short)(49 | (2 << 8)),
    (unsigned short)(50 | (2 << 8)), (unsigned short)(51 | (2 << 8)),
    (unsigned short)(52 | (2 << 8)), (unsigned short)(53 | (2 << 8)),
    // w7: vs 54,55 + vv1 72-79
    (unsigned short)(54 | (2 << 8)), (unsigned short)(55 | (2 << 8)),
    (unsigned short)(72 | (2 << 8)), (unsigned short)(73 | (2 << 8)),
    (unsigned short)(74 | (2 << 8)), (unsigned short)(75 | (2 << 8)),
    (unsigned short)(76 | (2 << 8)), (unsigned short)(77 | (2 << 8)),
    (unsigned short)(78 | (2 << 8)), (unsigned short)(79 | (2 << 8))};

__device__ __forceinline__ unsigned long long pack2(float x) {
    unsigned long long r;
    asm("mov.b64 %0, {%1, %1};" : "=l"(r) : "r"(__float_as_uint(x)));
    return r;
}
__device__ __forceinline__ unsigned long long ffma2(unsigned long long a,
                                                    unsigned long long b,
                                                    unsigned long long c) {
    unsigned long long d;
    asm("fma.rn.f32x2 %0, %1, %2, %3;" : "=l"(d) : "l"(a), "l"(b), "l"(c));
    return d;
}

// ew (packed pairs, 8x u64 = 16 edges) = b2[j] + sum_h hid[e][h] * W2[h][j]
__device__ __forceinline__ void mlp2_col(const float* __restrict__ W2,
                                         const float* __restrict__ b2,
                                         int j, const float* sm_hid,
                                         unsigned long long* ew) {
    unsigned long long bi = pack2(__ldg(b2 + j));
#pragma unroll
    for (int p = 0; p < 8; p++) ew[p] = bi;
    const float* wc = W2 + j;
#pragma unroll 8
    for (int hh = 0; hh < HIDF; hh++) {
        unsigned long long wp = pack2(__ldg(wc));
        wc += WNUMF;
        const ulonglong2* hp =
            reinterpret_cast<const ulonglong2*>(sm_hid + hh * TE);
        ulonglong2 a0 = hp[0], a1 = hp[1], a2 = hp[2], a3 = hp[3];
        ew[0] = ffma2(a0.x, wp, ew[0]);
        ew[1] = ffma2(a0.y, wp, ew[1]);
        ew[2] = ffma2(a1.x, wp, ew[2]);
        ew[3] = ffma2(a1.y, wp, ew[3]);
        ew[4] = ffma2(a2.x, wp, ew[4]);
        ew[5] = ffma2(a2.y, wp, ew[5]);
        ew[6] = ffma2(a3.x, wp, ew[6]);
        ew[7] = ffma2(a3.y, wp, ew[7]);
    }
}

// accumulate ew * fac into an owned smem slice (read-modify-write, no races)
__device__ __forceinline__ void rmw_slice(float* slice, const float* fac,
                                          const unsigned long long* ew) {
    const ulonglong2* fp = reinterpret_cast<const ulonglong2*>(fac);
    ulonglong2 f0 = fp[0], f1 = fp[1], f2 = fp[2], f3 = fp[3];
    ulonglong2* sp = reinterpret_cast<ulonglong2*>(slice);
    ulonglong2 s0 = sp[0], s1 = sp[1], s2 = sp[2], s3 = sp[3];
    s0.x = ffma2(ew[0], f0.x, s0.x);
    s0.y = ffma2(ew[1], f0.y, s0.y);
    s1.x = ffma2(ew[2], f1.x, s1.x);
    s1.y = ffma2(ew[3], f1.y, s1.y);
    s2.x = ffma2(ew[4], f2.x, s2.x);
    s2.y = ffma2(ew[5], f2.y, s2.y);
    s3.x = ffma2(ew[6], f3.x, s3.x);
    s3.y = ffma2(ew[7], f3.y, s3.y);
    sp[0] = s0; sp[1] = s1; sp[2] = s2; sp[3] = s3;
}

__global__ void zero_kernel() {
    int i = blockIdx.x * 256 + threadIdx.x;
    if (i < N_NODES * DIMF) g_agg[i] = 0.0f;
    if (i < N_NODES) g_cnt[i] = 0.0f;
}

__global__ __launch_bounds__(256, 2) void edge_kernel(
    const float* __restrict__ h, const float* __restrict__ pos,
    const int* __restrict__ ei, const float* __restrict__ means,
    const float* __restrict__ betas, const float* __restrict__ W1,
    const float* __restrict__ b1, const float* __restrict__ W2,
    const float* __restrict__ b2) {
    __shared__ __align__(16) float sm_hid[HIDF * TE];       // [h][e]
    __shared__ __align__(16) float sm_facS[48 * TE];        // sA[0..31], dot[32..47]
    __shared__ __align__(16) float sm_sB[32 * TE];
    __shared__ __align__(16) float sm_vP[16 * 3 * TE];      // [u][d][e]
    __shared__ __align__(16) float sm_crP[16 * 3 * TE];
    __shared__ float sm_y1[TE * 4];
    __shared__ float sm_rbf[TE * NUM_RBF];
    __shared__ float sm_expd[TE];
    __shared__ float sm_cut[TE];
    __shared__ int   sm_dst[TE];
    __shared__ int   sm_src[TE];
    __shared__ __align__(16) float sm_redS[5 * 32 * TE];     // [slot][w][e]
    __shared__ __align__(16) float sm_redQ[6 * 16 * TE];     // [slot][w'][e]
    __shared__ __align__(16) float sm_redV[4 * 16 * 3 * TE]; // [slot][w'][d][e]

    const int tid = threadIdx.x;
    const int lane = tid & 31;
    const int warp = tid >> 5;
    const int half = lane >> 4;
    const int e0 = blockIdx.x * TE;

    // ---- zero the partial-reduction buffers (RMW targets) ----
    {
        float4* z = reinterpret_cast<float4*>(sm_redS);
        // redS(2560) + redQ(1536) + redV(3072) floats are contiguous? not
        // guaranteed; zero each explicitly.
        for (int i = tid; i < 5 * 32 * TE / 4; i += 256)
            reinterpret_cast<float4*>(sm_redS)[i] = make_float4(0, 0, 0, 0);
        for (int i = tid; i < 6 * 16 * TE / 4; i += 256)
            reinterpret_cast<float4*>(sm_redQ)[i] = make_float4(0, 0, 0, 0);
        for (int i = tid; i < 4 * 16 * 3 * TE / 4; i += 256)
            reinterpret_cast<float4*>(sm_redV)[i] = make_float4(0, 0, 0, 0);
        (void)z;
    }

    // ---- Stage A1: geometry per edge (16 threads) ----
    if (tid < TE) {
        int eg = e0 + tid;
        int s = ei[eg], dd = ei[N_EDGES + eg];
        float vx = pos[dd * 3 + 0] - pos[s * 3 + 0];
        float vy = pos[dd * 3 + 1] - pos[s * 3 + 1];
        float vz = pos[dd * 3 + 2] - pos[s * 3 + 2];
        float d = sqrtf(vx * vx + vy * vy + vz * vz + 1e-12f);
        float inv = 1.7320508075688772f / d;  // sqrt(3)/d
        sm_y1[tid * 4 + 0] = vx * inv;
        sm_y1[tid * 4 + 1] = vy * inv;
        sm_y1[tid * 4 + 2] = vz * inv;
        sm_expd[tid] = expf(-d);  // ALPHA = 1
        sm_cut[tid] =
            (d < 5.0f) ? 0.5f * (cosf(d * 0.6283185307179586f) + 1.0f) : 0.0f;
        sm_src[tid] = s;
        sm_dst[tid] = dd;
    }
    __syncthreads();

    // ---- Stage A2: rbf (256 threads: e x r) ----
    {
        int e = tid >> 4, r = tid & 15;
        float t0 = sm_expd[e] - __ldg(means + r);
        sm_rbf[e * 16 + r] = expf(-__ldg(betas + r) * t0 * t0) * sm_cut[e];
    }
    __syncthreads();

    // ---- Stage B: hid = silu(rbf @ W1 + b1) ----
    {
        int e = tid >> 4, kk = tid & 15;
#pragma unroll
        for (int i = 0; i < 4; i++) {
            int k = kk + 16 * i;
            float a = __ldg(b1 + k);
#pragma unroll
            for (int r = 0; r < 16; r++)
                a += sm_rbf[e * 16 + r] * __ldg(W1 + r * HIDF + k);
            float sg = 1.0f / (1.0f + expf(-a));
            sm_hid[k * TE + e] = a * sg;
        }
    }
    // ---- Stage C: prescaled left factors ----
    {
        int e = tid >> 4, t = tid & 15;
        const float* hr = h + (size_t)sm_src[e] * DIMF;
        const float cS = 0.125f;                 // 1/(sqrt32*sqrt2)
        const float cQ = 0.10206207261596575f;   // 1/(sqrt32*sqrt3)
        const float cD = 0.17677669529663687f;   // 1/(sqrt16*sqrt2)
        const float cV = 0.14433756729740643f;   // 1/(sqrt16*sqrt3)
        const float cX = 0.10206207261596575f;   // 1/(sqrt2*sqrt16*sqrt3)
        float s0 = hr[t], s1 = hr[t + 16];
        sm_facS[t * TE + e] = s0 * cS;
        sm_facS[(t + 16) * TE + e] = s1 * cS;
        sm_sB[t * TE + e] = s0 * cQ;
        sm_sB[(t + 16) * TE + e] = s1 * cQ;
        float v0 = hr[32 + 3 * t + 0];
        float v1 = hr[32 + 3 * t + 1];
        float v2 = hr[32 + 3 * t + 2];
        sm_vP[(t * 3 + 0) * TE + e] = v0 * cV;
        sm_vP[(t * 3 + 1) * TE + e] = v1 * cV;
        sm_vP[(t * 3 + 2) * TE + e] = v2 * cV;
        float y0 = sm_y1[e * 4 + 0], y1v = sm_y1[e * 4 + 1],
              y2 = sm_y1[e * 4 + 2];
        float dt = (v0 * y0 + v1 * y1v + v2 * y2) * 0.5773502691896258f;
        sm_facS[(32 + t) * TE + e] = dt * cD;
        float c0 = v1 * y2 - v2 * y1v;
        float c1 = v2 * y0 - v0 * y2;
        float c2 = v0 * y1v - v1 * y0;
        sm_crP[(t * 3 + 0) * TE + e] = c0 * cX;
        sm_crP[(t * 3 + 1) * TE + e] = c1 * cX;
        sm_crP[(t * 3 + 2) * TE + e] = c2 * cX;
    }
    __syncthreads();

    // ---- Main fused GEMM + consume: 10 column-groups per warp ----
    {
        unsigned long long ew[8];
        const int qslot = (warp - 4) * 2 + half;  // valid for Q-type warps
        const int vslot = (warp - 6) * 2 + half;  // valid for V-type warps
#pragma unroll 1
        for (int t = 0; t < 10; t++) {
            unsigned short ent = c_sched[warp * 10 + t];
            int g = ent & 0xff;
            int typ = ent >> 8;
            int j = g * 32 + lane;
            mlp2_col(W2, b2, j, sm_hid, ew);
            if (typ == 0) {
                int fi = (g < 32) ? g : (g - 24);  // vv0: 32 + (g-56)
                rmw_slice(sm_redS + (warp * 32 + lane) * TE,
                          sm_facS + fi * TE, ew);
            } else if (typ == 1) {
                int u = 2 * (g - 32) + half;
                rmw_slice(sm_redQ + (qslot * 16 + (lane & 15)) * TE,
                          sm_sB + u * TE, ew);
            } else {
                const float* fb;
                int u;
                if (g < 72) { u = 2 * (g - 48) + half; fb = sm_vP; }
                else        { u = 2 * (g - 72) + half; fb = sm_crP; }
#pragma unroll
                for (int d = 0; d < 3; d++) {
                    rmw_slice(
                        sm_redV + ((vslot * 16 + (lane & 15)) * 3 + d) * TE,
                        fb + (u * 3 + d) * TE, ew);
                }
            }
        }
    }
    __syncthreads();

    // ---- Assemble messages + global atomic aggregation ----
    {
        int e = tid >> 4, t16 = tid & 15;
        int dd = sm_dst[e];
        float* aggrow = g_agg + (size_t)dd * DIMF;
#pragma unroll
        for (int i = 0; i < 5; i++) {
            int k = t16 + 16 * i;
            float val;
            if (k < 32) {
                float s = 0.0f;
#pragma unroll
                for (int p = 0; p < 5; p++)
                    s += sm_redS[(p * 32 + k) * TE + e];
                val = s;
            } else {
                int kk = k - 32;
                int w = kk / 3;
                int d = kk - 3 * w;
                float q2 = 0.0f;
#pragma unroll
                for (int p = 0; p < 6; p++)
                    q2 += sm_redQ[(p * 16 + w) * TE + e];
                float vv = 0.0f;
#pragma unroll
                for (int p = 0; p < 4; p++)
                    vv += sm_redV[((p * 16 + w) * 3 + d) * TE + e];
                val = q2 * sm_y1[e * 4 + d] + vv;
            }
            atomicAdd(aggrow + k, val);
        }
        if (t16 == 0) atomicAdd(g_cnt + dd, 1.0f);
    }
}

__global__ void combine_kernel(const float* __restrict__ h,
                               const float* __restrict__ Wss,
                               const float* __restrict__ Wvv,
                               float* __restrict__ out) {
    int idx = blockIdx.x * 256 + threadIdx.x;
    if (idx >= N_NODES * DIMF) return;
    int n = idx / DIMF;
    int k = idx - n * DIMF;
    const float* hr = h + (size_t)n * DIMF;
    float si;
    if (k < 32) {
        float s = 0.0f;
#pragma unroll
        for (int u = 0; u < 32; u++) s += hr[u] * __ldg(Wss + u * 32 + k);
        si = s * 0.17677669529663687f;  // 1/sqrt(32)
    } else {
        int kk = k - 32;
        int w = kk / 3;
        int d = kk - 3 * w;
        float s = 0.0f;
#pragma unroll
        for (int u = 0; u < 16; u++)
            s += hr[32 + 3 * u + d] * __ldg(Wvv + u * 16 + w);
        si = s * 0.25f;  // 1/sqrt(16)
    }
    float c = g_cnt[n];
    float a = g_agg[idx] / fmaxf(c, 1.0f);
    out[idx] = a + si + hr[k];
}

extern "C" void kernel_launch(void* const* d_in, const int* in_sizes, int n_in,
                              void* d_out, int out_size) {
    const float* h     = (const float*)d_in[0];
    const float* pos   = (const float*)d_in[1];
    const int*   ei    = (const int*)d_in[2];
    const float* means = (const float*)d_in[3];
    const float* betas = (const float*)d_in[4];
    const float* W1    = (const float*)d_in[5];
    const float* b1    = (const float*)d_in[6];
    const float* W2    = (const float*)d_in[7];
    const float* b2    = (const float*)d_in[8];
    const float* Wss   = (const float*)d_in[9];
    const float* Wvv   = (const float*)d_in[10];
    float* out = (float*)d_out;

    zero_kernel<<<(N_NODES * DIMF + 255) / 256, 256>>>();
    edge_kernel<<<N_EDGES / TE, 256>>>(h, pos, ei, means, betas, W1, b1, W2, b2);
    combine_kernel<<<(N_NODES * DIMF + 255) / 256, 256>>>(h, Wss, Wvv, out);
}

// round 7
// speedup vs baseline: 4.6422x; 2.5720x over previous
#include <cuda_runtime.h>
#include <cuda_bf16.h>
#include <cstdint>

#define N_NODES 8192
#define N_EDGES 32768
#define DIMF    80
#define HIDF    64
#define WNUMF   2560
#define EPC     128
#define NCHUNKS 20      // 20 x 128 cols

// ---- device scratch (allocation-free) ----
__device__ float g_agg[N_NODES * DIMF];
__device__ float g_cnt[N_NODES];
// W2 transposed: u32[n][p] = bf16x2(W2[2p][n], W2[2p+1][n]), swizzled p^((n&7)<<2)
__device__ uint32_t g_W2h[WNUMF * 32];
__device__ uint32_t g_W2l[WNUMF * 32];

// ---- smem offsets (bytes) ----
#define O_AH   0          // 128 x 32 u32 (hid hi, swizzled pairs)   16KB
#define O_AL   16384      //                                          16KB
#define O_BH0  32768      // B chunk buffers, 128 x 32 u32 each       16KB x4
#define O_BH1  49152
#define O_BL0  65536
#define O_BL1  81920
#define O_B2   98304      // 2560 f32                                 10KB
#define O_FS   108544     // 32 x 128 f32 (s * cS)                    16KB
#define O_FD   124928     // 16 x 128 f32 (dot * cD)                   8KB
#define O_FV   133120     // 48 x 128 f32 (v * cV)                    24KB
#define O_FC   157696     // 48 x 128 f32 (cross * cX)                24KB
#define O_Y1   182272     // 128 x 4 f32                               2KB
#define O_DST  184320     // 128 int
#define SMEM_TOTAL 184832

__device__ __forceinline__ uint32_t smem_u32(const void* p) {
    uint32_t a;
    asm("{ .reg .u64 t; cvta.to.shared.u64 t, %1; cvt.u32.u64 %0, t; }"
        : "=r"(a) : "l"(p));
    return a;
}
__device__ __forceinline__ void cp16(uint32_t saddr, const void* gp) {
    asm volatile("cp.async.cg.shared.global [%0], [%1], 16;"
                 :: "r"(saddr), "l"(gp) : "memory");
}
__device__ __forceinline__ void mma16816(float* d, const uint32_t* a,
                                         const uint32_t* b) {
    asm volatile(
        "mma.sync.aligned.m16n8k16.row.col.f32.bf16.bf16.f32 "
        "{%0,%1,%2,%3}, {%4,%5,%6,%7}, {%8,%9}, {%0,%1,%2,%3};"
        : "+f"(d[0]), "+f"(d[1]), "+f"(d[2]), "+f"(d[3])
        : "r"(a[0]), "r"(a[1]), "r"(a[2]), "r"(a[3]), "r"(b[0]), "r"(b[1]));
}

// ---- prep: zero agg/cnt + transpose/split/swizzle W2 ----
__global__ void prep_kernel(const float* __restrict__ W2) {
    int i = blockIdx.x * 256 + threadIdx.x;
    if (i < WNUMF * 32) {
        int n = i >> 5, p = i & 31;
        float w0 = W2[(size_t)(2 * p) * WNUMF + n];
        float w1 = W2[(size_t)(2 * p + 1) * WNUMF + n];
        __nv_bfloat16 h0 = __float2bfloat16(w0);
        __nv_bfloat16 h1 = __float2bfloat16(w1);
        __nv_bfloat16 l0 = __float2bfloat16(w0 - __bfloat162float(h0));
        __nv_bfloat16 l1 = __float2bfloat16(w1 - __bfloat162float(h1));
        int idx = n * 32 + (p ^ ((n & 7) << 2));
        g_W2h[idx] = ((uint32_t)__bfloat16_as_ushort(h1) << 16) |
                     __bfloat16_as_ushort(h0);
        g_W2l[idx] = ((uint32_t)__bfloat16_as_ushort(l1) << 16) |
                     __bfloat16_as_ushort(l0);
    }
    if (i < N_NODES * DIMF) g_agg[i] = 0.0f;
    if (i < N_NODES) g_cnt[i] = 0.0f;
}

__global__ __launch_bounds__(256, 1)
void edge_kernel(const float* __restrict__ h, const float* __restrict__ pos,
                 const int* __restrict__ ei, const float* __restrict__ means,
                 const float* __restrict__ betas, const float* __restrict__ W1,
                 const float* __restrict__ b1, const float* __restrict__ b2) {
    extern __shared__ char sm[];
    uint32_t* Ah = reinterpret_cast<uint32_t*>(sm + O_AH);
    uint32_t* Al = reinterpret_cast<uint32_t*>(sm + O_AL);
    float* B2s = reinterpret_cast<float*>(sm + O_B2);
    float* FS = reinterpret_cast<float*>(sm + O_FS);
    float* FD = reinterpret_cast<float*>(sm + O_FD);
    float* FV = reinterpret_cast<float*>(sm + O_FV);
    float* FC = reinterpret_cast<float*>(sm + O_FC);
    float* Y1 = reinterpret_cast<float*>(sm + O_Y1);
    int* DSTS = reinterpret_cast<int*>(sm + O_DST);

    const int tid = threadIdx.x;
    const int lane = tid & 31, warp = tid >> 5;
    const int g = lane >> 2, q = lane & 3;

    // ================= prologue =================
    const int el = tid & 127;   // local edge
    const int kh = tid >> 7;    // which k-half this thread computes
    const int e = blockIdx.x * EPC + el;
    const int s = ei[e], dd = ei[N_EDGES + e];
    float vx = pos[dd * 3 + 0] - pos[s * 3 + 0];
    float vy = pos[dd * 3 + 1] - pos[s * 3 + 1];
    float vz = pos[dd * 3 + 2] - pos[s * 3 + 2];
    float dist = sqrtf(vx * vx + vy * vy + vz * vz + 1e-12f);
    float inv = 1.7320508075688772f / dist;
    float y1x = vx * inv, y1y = vy * inv, y1z = vz * inv;
    float expd = expf(-dist);
    float cut =
        (dist < 5.0f) ? 0.5f * (cosf(dist * 0.6283185307179586f) + 1.0f) : 0.0f;

    float rbf[16];
#pragma unroll
    for (int r = 0; r < 16; r++) {
        float t0 = expd - __ldg(means + r);
        rbf[r] = expf(-__ldg(betas + r) * t0 * t0) * cut;
    }
    // hid = silu(rbf @ W1 + b1) for this thread's 32 k's -> A tiles (hi/lo)
#pragma unroll 4
    for (int k = kh * 32; k < kh * 32 + 32; k += 2) {
        float a0 = __ldg(b1 + k), a1 = __ldg(b1 + k + 1);
#pragma unroll
        for (int r = 0; r < 16; r++) {
            a0 += rbf[r] * __ldg(W1 + r * HIDF + k);
            a1 += rbf[r] * __ldg(W1 + r * HIDF + k + 1);
        }
        a0 = a0 / (1.0f + expf(-a0));
        a1 = a1 / (1.0f + expf(-a1));
        __nv_bfloat16 h0 = __float2bfloat16(a0);
        __nv_bfloat16 h1 = __float2bfloat16(a1);
        __nv_bfloat16 l0 = __float2bfloat16(a0 - __bfloat162float(h0));
        __nv_bfloat16 l1 = __float2bfloat16(a1 - __bfloat162float(h1));
        int p = k >> 1;
        int idx = el * 32 + (p ^ ((el & 7) << 2));
        Ah[idx] = ((uint32_t)__bfloat16_as_ushort(h1) << 16) |
                  __bfloat16_as_ushort(h0);
        Al[idx] = ((uint32_t)__bfloat16_as_ushort(l1) << 16) |
                  __bfloat16_as_ushort(l0);
    }
    if (tid < 128) {
        const float* hr = h + (size_t)s * DIMF;
        const float cS = 0.125f;
        const float cD = 0.17677669529663687f;
        const float cV = 0.14433756729740643f;
        const float cX = 0.10206207261596575f;
#pragma unroll
        for (int u = 0; u < 32; u++) FS[u * 128 + el] = __ldg(hr + u) * cS;
#pragma unroll
        for (int u = 0; u < 16; u++) {
            float v0 = __ldg(hr + 32 + 3 * u + 0);
            float v1 = __ldg(hr + 32 + 3 * u + 1);
            float v2 = __ldg(hr + 32 + 3 * u + 2);
            FV[(3 * u + 0) * 128 + el] = v0 * cV;
            FV[(3 * u + 1) * 128 + el] = v1 * cV;
            FV[(3 * u + 2) * 128 + el] = v2 * cV;
            float dt = (v0 * y1x + v1 * y1y + v2 * y1z) * 0.5773502691896258f;
            FD[u * 128 + el] = dt * cD;
            FC[(3 * u + 0) * 128 + el] = (v1 * y1z - v2 * y1y) * cX;
            FC[(3 * u + 1) * 128 + el] = (v2 * y1x - v0 * y1z) * cX;
            FC[(3 * u + 2) * 128 + el] = (v0 * y1y - v1 * y1x) * cX;
        }
        Y1[el * 4 + 0] = y1x;
        Y1[el * 4 + 1] = y1y;
        Y1[el * 4 + 2] = y1z;
        DSTS[el] = dd;
    }
    for (int i = tid; i < WNUMF; i += 256) B2s[i] = __ldg(b2 + i);
    // chunk 0 (plain copy)
    {
        const uint4* gh = reinterpret_cast<const uint4*>(g_W2h);
        const uint4* gl = reinterpret_cast<const uint4*>(g_W2l);
        uint4* bh = reinterpret_cast<uint4*>(sm + O_BH0);
        uint4* bl = reinterpret_cast<uint4*>(sm + O_BL0);
#pragma unroll
        for (int t = 0; t < 4; t++) {
            int i = tid + 256 * t;
            bh[i] = gh[i];
            bl[i] = gl[i];
        }
    }
    __syncthreads();

    // ================= A fragments (persistent) =================
    const int wb = warp * 16;
    const int r0 = wb + g, r1 = wb + g + 8;
    uint32_t ahf[16], alf[16];
#pragma unroll
    for (int T = 0; T < 4; T++) {
        int p0 = 8 * T + q, p1 = p0 + 4;
        int sw = g << 2;
        ahf[4 * T + 0] = Ah[r0 * 32 + (p0 ^ sw)];
        ahf[4 * T + 1] = Ah[r1 * 32 + (p0 ^ sw)];
        ahf[4 * T + 2] = Ah[r0 * 32 + (p1 ^ sw)];
        ahf[4 * T + 3] = Ah[r1 * 32 + (p1 ^ sw)];
        alf[4 * T + 0] = Al[r0 * 32 + (p0 ^ sw)];
        alf[4 * T + 1] = Al[r1 * 32 + (p0 ^ sw)];
        alf[4 * T + 2] = Al[r0 * 32 + (p1 ^ sw)];
        alf[4 * T + 3] = Al[r1 * 32 + (p1 ^ sw)];
    }

    // per-thread disjoint message accumulators: [2 rows] x channels
    float os[16], q2a[8], ov[24];
#pragma unroll
    for (int i = 0; i < 16; i++) os[i] = 0.0f;
#pragma unroll
    for (int i = 0; i < 8; i++) q2a[i] = 0.0f;
#pragma unroll
    for (int i = 0; i < 24; i++) ov[i] = 0.0f;

    const uint32_t smb = smem_u32(sm);

    // ================= main N sweep =================
#pragma unroll 1
    for (int c = 0; c < NCHUNKS; c++) {
        if (c + 1 < NCHUNKS) {  // prefetch next chunk via cp.async
            uint32_t dh = smb + (((c + 1) & 1) ? O_BH1 : O_BH0);
            uint32_t dl = smb + (((c + 1) & 1) ? O_BL1 : O_BL0);
            const uint4* gh =
                reinterpret_cast<const uint4*>(g_W2h) + (c + 1) * 1024;
            const uint4* gl =
                reinterpret_cast<const uint4*>(g_W2l) + (c + 1) * 1024;
#pragma unroll
            for (int t = 0; t < 4; t++) {
                int i = tid + 256 * t;
                cp16(dh + 16 * i, gh + i);
                cp16(dl + 16 * i, gl + i);
            }
            asm volatile("cp.async.commit_group;" ::: "memory");
        }
        const uint32_t* Bhc =
            reinterpret_cast<const uint32_t*>(sm + ((c & 1) ? O_BH1 : O_BH0));
        const uint32_t* Blc =
            reinterpret_cast<const uint32_t*>(sm + ((c & 1) ? O_BL1 : O_BL0));

#pragma unroll 2
        for (int nt = 0; nt < 16; nt++) {
            uint32_t bh[8], bl[8];
            const int nn = nt * 8 + g;
            const int sw = g << 2;
#pragma unroll
            for (int T = 0; T < 4; T++) {
                int p0 = 8 * T + q;
                bh[2 * T]     = Bhc[nn * 32 + (p0 ^ sw)];
                bh[2 * T + 1] = Bhc[nn * 32 + ((p0 + 4) ^ sw)];
                bl[2 * T]     = Blc[nn * 32 + (p0 ^ sw)];
                bl[2 * T + 1] = Blc[nn * 32 + ((p0 + 4) ^ sw)];
            }
            float a1[4] = {0, 0, 0, 0}, a2[4] = {0, 0, 0, 0},
                  a3[4] = {0, 0, 0, 0};
#pragma unroll
            for (int T = 0; T < 4; T++) {
                mma16816(a1, ahf + 4 * T, bh + 2 * T);
                mma16816(a2, ahf + 4 * T, bl + 2 * T);
                mma16816(a3, alf + 4 * T, bh + 2 * T);
            }
            const int NT = c * 16 + nt;
            float2 bb = *reinterpret_cast<const float2*>(B2s + NT * 8 + 2 * q);
            float v0 = a1[0] + a2[0] + a3[0] + bb.x;
            float v1 = a1[1] + a2[1] + a3[1] + bb.y;
            float v2 = a1[2] + a2[2] + a3[2] + bb.x;
            float v3 = a1[3] + a2[3] + a3[3] + bb.y;
            const int G = NT >> 2, m = NT & 3;
            if (G < 32 || (G >= 56 && G < 72)) {           // ss | vv0 -> out_s
                const float* F = (G < 32) ? FS : FD;
                int u = (G < 32) ? G : (G - 56);
                float f0 = F[u * 128 + r0], f1 = F[u * 128 + r1];
                int sl = m * 2;
                os[sl] += f0 * v0;
                os[sl + 1] += f0 * v1;
                os[8 + sl] += f1 * v2;
                os[8 + sl + 1] += f1 * v3;
            } else if (G < 48) {                           // sv -> q2
                int u = 2 * (G - 32) + (m >> 1);
                float f0 = FS[u * 128 + r0] * 0.8164965809277261f;
                float f1 = FS[u * 128 + r1] * 0.8164965809277261f;
                int sl = (m & 1) * 2;
                q2a[sl] += f0 * v0;
                q2a[sl + 1] += f0 * v1;
                q2a[4 + sl] += f1 * v2;
                q2a[4 + sl + 1] += f1 * v3;
            } else {                                       // vs | vv1 -> ov
                const float* F = (G < 56) ? FV : FC;
                int u = (G < 56) ? (2 * (G - 48) + (m >> 1))
                                 : (2 * (G - 72) + (m >> 1));
                int sl = (m & 1) * 2;
#pragma unroll
                for (int d = 0; d < 3; d++) {
                    float f0 = F[(3 * u + d) * 128 + r0];
                    float f1 = F[(3 * u + d) * 128 + r1];
                    ov[sl * 3 + d] += f0 * v0;
                    ov[(sl + 1) * 3 + d] += f0 * v1;
                    ov[12 + sl * 3 + d] += f1 * v2;
                    ov[12 + (sl + 1) * 3 + d] += f1 * v3;
                }
            }
        }
        if (c + 1 < NCHUNKS) {
            asm volatile("cp.async.wait_group 0;" ::: "memory");
            __syncthreads();
        }
    }

    // ================= writeout (disjoint channels per thread) =================
#pragma unroll
    for (int r = 0; r < 2; r++) {
        int eloc = wb + g + 8 * r;
        int dn = DSTS[eloc];
        float* row = g_agg + (size_t)dn * DIMF;
#pragma unroll
        for (int sl = 0; sl < 8; sl++) {
            int w = (sl >> 1) * 8 + 2 * q + (sl & 1);
            atomicAdd(row + w, os[r * 8 + sl]);
        }
        float yy0 = Y1[eloc * 4 + 0], yy1 = Y1[eloc * 4 + 1],
              yy2 = Y1[eloc * 4 + 2];
#pragma unroll
        for (int s2 = 0; s2 < 4; s2++) {
            int wq = (s2 >> 1) * 8 + 2 * q + (s2 & 1);
            float qv = q2a[r * 4 + s2];
            atomicAdd(row + 32 + 3 * wq + 0, ov[r * 12 + s2 * 3 + 0] + qv * yy0);
            atomicAdd(row + 32 + 3 * wq + 1, ov[r * 12 + s2 * 3 + 1] + qv * yy1);
            atomicAdd(row + 32 + 3 * wq + 2, ov[r * 12 + s2 * 3 + 2] + qv * yy2);
        }
        if (q == 0) atomicAdd(g_cnt + dn, 1.0f);
    }
}

__global__ void combine_kernel(const float* __restrict__ h,
                               const float* __restrict__ Wss,
                               const float* __restrict__ Wvv,
                               float* __restrict__ out) {
    int idx = blockIdx.x * 256 + threadIdx.x;
    if (idx >= N_NODES * DIMF) return;
    int n = idx / DIMF;
    int k = idx - n * DIMF;
    const float* hr = h + (size_t)n * DIMF;
    float si;
    if (k < 32) {
        float s = 0.0f;
#pragma unroll
        for (int u = 0; u < 32; u++) s += hr[u] * __ldg(Wss + u * 32 + k);
        si = s * 0.17677669529663687f;  // 1/sqrt(32)
    } else {
        int kk = k - 32;
        int w = kk / 3;
        int d = kk - 3 * w;
        float s = 0.0f;
#pragma unroll
        for (int u = 0; u < 16; u++)
            s += hr[32 + 3 * u + d] * __ldg(Wvv + u * 16 + w);
        si = s * 0.25f;  // 1/sqrt(16)
    }
    float c = g_cnt[n];
    float a = g_agg[idx] / fmaxf(c, 1.0f);
    out[idx] = a + si + hr[k];
}

extern "C" void kernel_launch(void* const* d_in, const int* in_sizes, int n_in,
                              void* d_out, int out_size) {
    const float* h     = (const float*)d_in[0];
    const float* pos   = (const float*)d_in[1];
    const int*   ei    = (const int*)d_in[2];
    const float* means = (const float*)d_in[3];
    const float* betas = (const float*)d_in[4];
    const float* W1    = (const float*)d_in[5];
    const float* b1    = (const float*)d_in[6];
    const float* W2    = (const float*)d_in[7];
    const float* b2    = (const float*)d_in[8];
    const float* Wss   = (const float*)d_in[9];
    const float* Wvv   = (const float*)d_in[10];
    float* out = (float*)d_out;

    cudaFuncSetAttribute(edge_kernel,
                         cudaFuncAttributeMaxDynamicSharedMemorySize, SMEM_TOTAL);

    prep_kernel<<<(N_NODES * DIMF + 255) / 256, 256>>>(W2);
    edge_kernel<<<N_EDGES / EPC, 256, SMEM_TOTAL>>>(h, pos, ei, means, betas,
                                                    W1, b1, b2);
    combine_kernel<<<(N_NODES * DIMF + 255) / 256, 256>>>(h, Wss, Wvv, out);
}